// round 3
// baseline (speedup 1.0000x reference)
#include <cuda_runtime.h>
#include <cstdint>

// x (256,18,18,512) f32, W (18,512,512) f32, b (18,512) f32, idx (18) i32
#define KB_   256
#define O_    18
#define J_    18
#define DIM   512
#define M_TOTAL (KB_ * J_)        // 4608
#define BM    128
#define BN    256
#define BK    16
#define ST    20                  // smem row stride (u32): BK + 4 pad
#define NKT   (DIM / BK)          // 32
#define SCALE_F 0.044194173824159216f

#define SA_STAGE (BM * ST)        // 2560 u32
#define SB_STAGE (BN * ST)        // 5120 u32
#define SMEM_U32 (2 * (SA_STAGE + SB_STAGE))   // 15360 u32 = 61440 B

__device__ int g_sel[J_];

__global__ void build_sel_kernel(const int* __restrict__ idx, int n) {
    int t = threadIdx.x;
    if (t < J_) g_sel[t] = 0;
    __syncthreads();
    if (t < n) {
        int v = idx[t];
        if (v >= 0 && v < J_) g_sel[v] = 1;
    }
}

__device__ __forceinline__ uint32_t f2tf32(float f) {
    uint32_t u;
    asm("cvt.rna.tf32.f32 %0, %1;" : "=r"(u) : "f"(f));
    return u;
}

__global__ __launch_bounds__(256)
void dirnet_gemm_kernel(const float* __restrict__ x, const float* __restrict__ W,
                        const float* __restrict__ bias, float* __restrict__ out) {
    extern __shared__ uint32_t sm[];
    uint32_t* sA = sm;                       // [2][SA_STAGE]
    uint32_t* sB = sm + 2 * SA_STAGE;        // [2][SB_STAGE]

    const int o   = blockIdx.z;
    const int mt  = blockIdx.y;
    const int nt  = blockIdx.x;
    const int tid = threadIdx.x;
    const int lane = tid & 31;
    const int wid  = tid >> 5;
    const int g  = lane >> 2;   // 0..7
    const int t4 = lane & 3;    // 0..3
    const int wm = wid >> 2;    // 0..1 -> 64 rows
    const int wn = wid & 3;     // 0..3 -> 64 cols

    // ---- producer addressing ----
    // A: 512 float4 per k-tile -> 2 per thread.  B: 1024 float4 -> 4 per thread.
    int aOff[2], sAOff[2];
    #pragma unroll
    for (int it = 0; it < 2; it++) {
        int f = tid + it * 256;
        int row = f >> 2, c4 = f & 3;
        int m = mt * BM + row;
        int kb = m / J_;
        int j = m - kb * J_;
        aOff[it]  = ((kb * O_ + o) * J_ + j) * DIM + c4 * 4;
        sAOff[it] = row * ST + c4 * 4;
    }
    int bOff[4], sBOff[4];
    #pragma unroll
    for (int it = 0; it < 4; it++) {
        int f = tid + it * 256;
        int row = f >> 2, c4 = f & 3;
        bOff[it]  = o * (DIM * DIM) + (nt * BN + row) * DIM + c4 * 4;
        sBOff[it] = row * ST + c4 * 4;
    }

    float4 ra[2], rb[4];
    #pragma unroll
    for (int it = 0; it < 2; it++) ra[it] = *reinterpret_cast<const float4*>(x + aOff[it]);
    #pragma unroll
    for (int it = 0; it < 4; it++) rb[it] = *reinterpret_cast<const float4*>(W + bOff[it]);

    #pragma unroll
    for (int it = 0; it < 2; it++) {
        uint4 u = make_uint4(f2tf32(ra[it].x), f2tf32(ra[it].y), f2tf32(ra[it].z), f2tf32(ra[it].w));
        *reinterpret_cast<uint4*>(&sA[sAOff[it]]) = u;
    }
    #pragma unroll
    for (int it = 0; it < 4; it++) {
        uint4 u = make_uint4(f2tf32(rb[it].x), f2tf32(rb[it].y), f2tf32(rb[it].z), f2tf32(rb[it].w));
        *reinterpret_cast<uint4*>(&sB[sBOff[it]]) = u;
    }
    __syncthreads();

    float acc[4][8][4];
    #pragma unroll
    for (int a = 0; a < 4; a++)
        #pragma unroll
        for (int b = 0; b < 8; b++)
            #pragma unroll
            for (int c = 0; c < 4; c++) acc[a][b][c] = 0.f;

    const int mBase = wm * 64;
    const int nBase = wn * 64;

    for (int kt = 0; kt < NKT; kt++) {
        const int cur = kt & 1;
        const uint32_t* cA = sA + cur * SA_STAGE;
        const uint32_t* cB = sB + cur * SB_STAGE;

        if (kt < NKT - 1) {
            #pragma unroll
            for (int it = 0; it < 2; it++)
                ra[it] = *reinterpret_cast<const float4*>(x + aOff[it] + (kt + 1) * BK);
            #pragma unroll
            for (int it = 0; it < 4; it++)
                rb[it] = *reinterpret_cast<const float4*>(W + bOff[it] + (kt + 1) * BK);
        }

        #pragma unroll
        for (int ks = 0; ks < 2; ks++) {
            const int k0 = ks * 8;
            uint32_t af[4][4], bf[8][2];
            #pragma unroll
            for (int mf = 0; mf < 4; mf++) {
                int r = (mBase + mf * 16 + g) * ST + k0 + t4;
                af[mf][0] = cA[r];
                af[mf][1] = cA[r + 8 * ST];
                af[mf][2] = cA[r + 4];
                af[mf][3] = cA[r + 8 * ST + 4];
            }
            #pragma unroll
            for (int nf = 0; nf < 8; nf++) {
                int r = (nBase + nf * 8 + g) * ST + k0 + t4;
                bf[nf][0] = cB[r];
                bf[nf][1] = cB[r + 4];
            }
            #pragma unroll
            for (int mf = 0; mf < 4; mf++)
                #pragma unroll
                for (int nf = 0; nf < 8; nf++) {
                    asm volatile(
                        "mma.sync.aligned.m16n8k8.row.col.f32.tf32.tf32.f32 "
                        "{%0,%1,%2,%3}, {%4,%5,%6,%7}, {%8,%9}, {%0,%1,%2,%3};\n"
                        : "+f"(acc[mf][nf][0]), "+f"(acc[mf][nf][1]),
                          "+f"(acc[mf][nf][2]), "+f"(acc[mf][nf][3])
                        : "r"(af[mf][0]), "r"(af[mf][1]), "r"(af[mf][2]), "r"(af[mf][3]),
                          "r"(bf[nf][0]), "r"(bf[nf][1]));
                }
        }

        if (kt < NKT - 1) {
            const int nxt = cur ^ 1;
            uint32_t* nA = sA + nxt * SA_STAGE;
            uint32_t* nB = sB + nxt * SB_STAGE;
            __syncthreads();   // all warps done reading 'nxt' from 2 tiles ago
            #pragma unroll
            for (int it = 0; it < 2; it++) {
                uint4 u = make_uint4(f2tf32(ra[it].x), f2tf32(ra[it].y),
                                     f2tf32(ra[it].z), f2tf32(ra[it].w));
                *reinterpret_cast<uint4*>(&nA[sAOff[it]]) = u;
            }
            #pragma unroll
            for (int it = 0; it < 4; it++) {
                uint4 u = make_uint4(f2tf32(rb[it].x), f2tf32(rb[it].y),
                                     f2tf32(rb[it].z), f2tf32(rb[it].w));
                *reinterpret_cast<uint4*>(&nB[sBOff[it]]) = u;
            }
            __syncthreads();
        }
    }

    // ---- epilogue: y = acc*SCALE + b[o] for selected rows, else passthrough x ----
    const float* bRow = bias + o * DIM + nt * BN;
    #pragma unroll
    for (int mf = 0; mf < 4; mf++) {
        #pragma unroll
        for (int half = 0; half < 2; half++) {
            int mloc = mBase + mf * 16 + g + half * 8;
            int m  = mt * BM + mloc;
            int kb = m / J_;
            int j  = m - kb * J_;
            int rowOff = ((kb * O_ + o) * J_ + j) * DIM + nt * BN;
            int selv = g_sel[j];
            #pragma unroll
            for (int nf = 0; nf < 8; nf++) {
                int n = nBase + nf * 8 + t4 * 2;
                float v0, v1;
                if (selv) {
                    v0 = acc[mf][nf][half * 2 + 0] * SCALE_F + bRow[n];
                    v1 = acc[mf][nf][half * 2 + 1] * SCALE_F + bRow[n + 1];
                } else {
                    v0 = x[rowOff + n];
                    v1 = x[rowOff + n + 1];
                }
                *reinterpret_cast<float2*>(out + rowOff + n) = make_float2(v0, v1);
            }
        }
    }
}

extern "C" void kernel_launch(void* const* d_in, const int* in_sizes, int n_in,
                              void* d_out, int out_size) {
    const float* x   = (const float*)d_in[0];
    const float* W   = (const float*)d_in[1];
    const float* b   = (const float*)d_in[2];
    const int*   idx = (const int*)d_in[3];
    float* out = (float*)d_out;

    build_sel_kernel<<<1, 32>>>(idx, in_sizes[3]);

    cudaFuncSetAttribute(dirnet_gemm_kernel,
                         cudaFuncAttributeMaxDynamicSharedMemorySize, SMEM_U32 * 4);

    dim3 grid(DIM / BN, M_TOTAL / BM, O_);
    dirnet_gemm_kernel<<<grid, 256, SMEM_U32 * 4>>>(x, W, b, out);
}

// round 4
// speedup vs baseline: 1.2274x; 1.2274x over previous
#include <cuda_runtime.h>
#include <cstdint>

// x (256,18,18,512) f32, W (18,512,512) f32, b (18,512) f32, idx (18) i32
#define KB_   256
#define O_    18
#define J_    18
#define DIM   512
#define M_TOTAL (KB_ * J_)        // 4608
#define BM    128
#define BN    128
#define BK    16
#define ST    20                  // smem row stride (u32): BK + 4 pad (bank-clean, proven R1)
#define NKT   (DIM / BK)          // 32
#define STAGES 3
#define SCALE_F 0.044194173824159216f

#define SA_U32 (BM * ST)                    // 2560
#define SB_U32 (BN * ST)                    // 2560
#define STG_U32 (SA_U32 + SB_U32)           // 5120
#define SMEM_BYTES (STAGES * STG_U32 * 4)   // 61440

__device__ int g_sel[J_];
__device__ float g_Wt[O_ * DIM * DIM];      // W pre-converted to tf32 bit patterns

__global__ void build_sel_kernel(const int* __restrict__ idx, int n) {
    int t = threadIdx.x;
    if (t < J_) g_sel[t] = 0;
    __syncthreads();
    if (t < n) {
        int v = idx[t];
        if (v >= 0 && v < J_) g_sel[v] = 1;
    }
}

__device__ __forceinline__ uint32_t f2tf32(float f) {
    uint32_t u;
    asm("cvt.rna.tf32.f32 %0, %1;" : "=r"(u) : "f"(f));
    return u;
}

__global__ void convert_w_kernel(const float* __restrict__ W) {
    const int total4 = O_ * DIM * DIM / 4;
    for (int i = blockIdx.x * blockDim.x + threadIdx.x; i < total4;
         i += gridDim.x * blockDim.x) {
        float4 v = reinterpret_cast<const float4*>(W)[i];
        uint4 u = make_uint4(f2tf32(v.x), f2tf32(v.y), f2tf32(v.z), f2tf32(v.w));
        reinterpret_cast<uint4*>(g_Wt)[i] = u;
    }
}

__device__ __forceinline__ uint32_t smem_u32(const void* p) {
    uint32_t a;
    asm("{ .reg .u64 t; cvta.to.shared.u64 t, %1; cvt.u32.u64 %0, t; }" : "=r"(a) : "l"(p));
    return a;
}

__device__ __forceinline__ void cp16(uint32_t dst, const void* src) {
    asm volatile("cp.async.cg.shared.global [%0], [%1], 16;" :: "r"(dst), "l"(src));
}

__global__ __launch_bounds__(256, 2)
void dirnet_gemm_kernel(const float* __restrict__ x, const float* __restrict__ bias,
                        float* __restrict__ out) {
    extern __shared__ uint32_t sm[];
    const uint32_t smb = smem_u32(sm);

    const int o   = blockIdx.z;
    const int mt  = blockIdx.y;
    const int nt  = blockIdx.x;
    const int tid = threadIdx.x;
    const int lane = tid & 31;
    const int wid  = tid >> 5;
    const int g  = lane >> 2;   // 0..7
    const int t4 = lane & 3;    // 0..3
    const int wm = wid >> 2;    // 0..1 -> 64 rows
    const int wn = wid & 3;     // 0..3 -> 32 cols

    // ---- producer addressing: per thread 2 float4 of A and 2 of B per k-tile ----
    int aOff[2], bOff[2], tOff[2];
    #pragma unroll
    for (int it = 0; it < 2; it++) {
        int f   = it * 256 + tid;
        int row = f >> 2;        // 0..127
        int c4  = f & 3;
        int m   = mt * BM + row;
        int kb  = m / J_;
        int j   = m - kb * J_;
        aOff[it] = ((kb * O_ + o) * J_ + j) * DIM + c4 * 4;
        bOff[it] = o * (DIM * DIM) + (nt * BN + row) * DIM + c4 * 4;
        tOff[it] = row * ST + c4 * 4;  // u32 offset within a stage's A (or B) block
    }

    float4 ra[2];

    // ---- prologue: stages 0,1 in flight; A(2) LDG issued ----
    #pragma unroll
    for (int s = 0; s < 2; s++) {
        uint32_t base = smb + s * STG_U32 * 4;
        #pragma unroll
        for (int it = 0; it < 2; it++) {
            float4 v = *reinterpret_cast<const float4*>(x + aOff[it] + s * BK);
            uint4 u = make_uint4(f2tf32(v.x), f2tf32(v.y), f2tf32(v.z), f2tf32(v.w));
            *reinterpret_cast<uint4*>(&sm[s * STG_U32 + tOff[it]]) = u;
            cp16(base + (SA_U32 + tOff[it]) * 4, g_Wt + bOff[it] + s * BK);
        }
        asm volatile("cp.async.commit_group;" ::: "memory");
    }
    #pragma unroll
    for (int it = 0; it < 2; it++)
        ra[it] = *reinterpret_cast<const float4*>(x + aOff[it] + 2 * BK);

    float acc[4][4][4];
    #pragma unroll
    for (int a = 0; a < 4; a++)
        #pragma unroll
        for (int b = 0; b < 4; b++)
            #pragma unroll
            for (int c = 0; c < 4; c++) acc[a][b][c] = 0.f;

    const int mBase = wm * 64;
    const int nBase = wn * 32;

    for (int kt = 0; kt < NKT; kt++) {
        const int cur = kt % STAGES;
        asm volatile("cp.async.wait_group 1;" ::: "memory");
        __syncthreads();

        // refill stage kt+2 (the one consumed at kt-1)
        if (kt + 2 < NKT) {
            const int nxt = (kt + 2) % STAGES;
            uint32_t base = smb + nxt * STG_U32 * 4;
            #pragma unroll
            for (int it = 0; it < 2; it++) {
                uint4 u = make_uint4(f2tf32(ra[it].x), f2tf32(ra[it].y),
                                     f2tf32(ra[it].z), f2tf32(ra[it].w));
                *reinterpret_cast<uint4*>(&sm[nxt * STG_U32 + tOff[it]]) = u;
                cp16(base + (SA_U32 + tOff[it]) * 4, g_Wt + bOff[it] + (kt + 2) * BK);
            }
        }
        asm volatile("cp.async.commit_group;" ::: "memory");
        if (kt + 3 < NKT) {
            #pragma unroll
            for (int it = 0; it < 2; it++)
                ra[it] = *reinterpret_cast<const float4*>(x + aOff[it] + (kt + 3) * BK);
        }

        const uint32_t* cA = sm + cur * STG_U32;
        const uint32_t* cB = cA + SA_U32;

        #pragma unroll
        for (int ks = 0; ks < 2; ks++) {
            const int k0 = ks * 8;
            uint32_t af[4][4], bf[4][2];
            #pragma unroll
            for (int mf = 0; mf < 4; mf++) {
                int r = (mBase + mf * 16 + g) * ST + k0 + t4;
                af[mf][0] = cA[r];
                af[mf][1] = cA[r + 8 * ST];
                af[mf][2] = cA[r + 4];
                af[mf][3] = cA[r + 8 * ST + 4];
            }
            #pragma unroll
            for (int nf = 0; nf < 4; nf++) {
                int r = (nBase + nf * 8 + g) * ST + k0 + t4;
                bf[nf][0] = cB[r];
                bf[nf][1] = cB[r + 4];
            }
            #pragma unroll
            for (int mf = 0; mf < 4; mf++)
                #pragma unroll
                for (int nf = 0; nf < 4; nf++) {
                    asm volatile(
                        "mma.sync.aligned.m16n8k8.row.col.f32.tf32.tf32.f32 "
                        "{%0,%1,%2,%3}, {%4,%5,%6,%7}, {%8,%9}, {%0,%1,%2,%3};\n"
                        : "+f"(acc[mf][nf][0]), "+f"(acc[mf][nf][1]),
                          "+f"(acc[mf][nf][2]), "+f"(acc[mf][nf][3])
                        : "r"(af[mf][0]), "r"(af[mf][1]), "r"(af[mf][2]), "r"(af[mf][3]),
                          "r"(bf[nf][0]), "r"(bf[nf][1]));
                }
        }
    }

    // ---- epilogue ----
    const float* bRow = bias + o * DIM;
    #pragma unroll
    for (int mf = 0; mf < 4; mf++) {
        #pragma unroll
        for (int half = 0; half < 2; half++) {
            int mloc = mBase + mf * 16 + g + half * 8;
            int m  = mt * BM + mloc;
            int kb = m / J_;
            int j  = m - kb * J_;
            int rowOff = ((kb * O_ + o) * J_ + j) * DIM;
            int selv = g_sel[j];
            #pragma unroll
            for (int nf = 0; nf < 4; nf++) {
                int n = nt * BN + nBase + nf * 8 + t4 * 2;
                float v0, v1;
                if (selv) {
                    v0 = acc[mf][nf][half * 2 + 0] * SCALE_F + bRow[n];
                    v1 = acc[mf][nf][half * 2 + 1] * SCALE_F + bRow[n + 1];
                } else {
                    v0 = x[rowOff + n];
                    v1 = x[rowOff + n + 1];
                }
                *reinterpret_cast<float2*>(out + rowOff + n) = make_float2(v0, v1);
            }
        }
    }
}

extern "C" void kernel_launch(void* const* d_in, const int* in_sizes, int n_in,
                              void* d_out, int out_size) {
    const float* x   = (const float*)d_in[0];
    const float* W   = (const float*)d_in[1];
    const float* b   = (const float*)d_in[2];
    const int*   idx = (const int*)d_in[3];
    float* out = (float*)d_out;

    build_sel_kernel<<<1, 32>>>(idx, in_sizes[3]);
    convert_w_kernel<<<1024, 256>>>(W);

    cudaFuncSetAttribute(dirnet_gemm_kernel,
                         cudaFuncAttributeMaxDynamicSharedMemorySize, SMEM_BYTES);

    dim3 grid(DIM / BN, M_TOTAL / BM, O_);
    dirnet_gemm_kernel<<<grid, 256, SMEM_BYTES>>>(x, b, out);
}